// round 12
// baseline (speedup 1.0000x reference)
#include <cuda_runtime.h>
#include <cuda_bf16.h>
#include <math.h>

// Problem constants
#define BB 64
#define TT 512
#define II 1024
#define HH 1024
#define BH (BB * HH)        // 65536
#define TH ((size_t)TT * HH) // 524288

// Scratch: preactivation xp[t][b][h] = x@W_ih^T + b_ih + b_hh  (128 MB)
__device__ float g_xp[(size_t)TT * BB * HH];

// ---------------------------------------------------------------------------
// f32x2 helpers (Blackwell packed fp32 FMA: 2 MACs per instruction)
// ---------------------------------------------------------------------------
__device__ __forceinline__ unsigned long long dup2(float v) {
    unsigned long long r;
    asm("mov.b64 %0, {%1, %1};" : "=l"(r) : "r"(__float_as_uint(v)));
    return r;
}
__device__ __forceinline__ void ffma2(unsigned long long& acc,
                                      unsigned long long a,
                                      unsigned long long b) {
    asm("fma.rn.f32x2 %0, %1, %2, %0;" : "+l"(acc) : "l"(a), "l"(b));
}
__device__ __forceinline__ void unpack2(unsigned long long v, float& lo, float& hi) {
    unsigned int l, h;
    asm("mov.b64 {%0, %1}, %2;" : "=r"(l), "=r"(h) : "l"(v));
    lo = __uint_as_float(l);
    hi = __uint_as_float(h);
}

// ---------------------------------------------------------------------------
// Phase 1: xp GEMM.  C[r][n] = sum_i X[r][i] * W_ih[n][i],  r = b*T + t.
// Block tile: BM=64 rows x BN=32 cols, BK=32, 256 threads, microtile 4m x 2n.
// Double-buffered smem + register prefetch.
// ---------------------------------------------------------------------------
__global__ __launch_bounds__(256) void xp_gemm_kernel(
    const float* __restrict__ X,     // [B*T, I] (x is [B,T,I], row-contiguous)
    const float* __restrict__ Wih,   // [H, I]
    const float* __restrict__ bih,   // [H]
    const float* __restrict__ bhh)   // [H]
{
    __shared__ float As[2][64][32];      // [buf][m][k]
    __shared__ float Ws[2][32][34];      // [buf][k][n] (transposed, padded)

    const int tid = threadIdx.x;
    const int r0 = blockIdx.y * 64;
    const int n0 = blockIdx.x * 32;

    float4 ra[2], rw;

    auto loadA = [&](int kt) {
#pragma unroll
        for (int i = 0; i < 2; i++) {
            int idx = tid + 256 * i;
            int row = idx >> 3, kq = idx & 7;
            ra[i] = *(const float4*)(X + (size_t)(r0 + row) * II + kt * 32 + kq * 4);
        }
    };
    auto loadW = [&](int kt) {
        int row = tid >> 3, kq = tid & 7;
        rw = *(const float4*)(Wih + (size_t)(n0 + row) * II + kt * 32 + kq * 4);
    };
    auto storeT = [&](int buf) {
#pragma unroll
        for (int i = 0; i < 2; i++) {
            int idx = tid + 256 * i;
            int row = idx >> 3, kq = idx & 7;
            *(float4*)&As[buf][row][kq * 4] = ra[i];
        }
        int row = tid >> 3, kq = tid & 7;
        Ws[buf][kq * 4 + 0][row] = rw.x;
        Ws[buf][kq * 4 + 1][row] = rw.y;
        Ws[buf][kq * 4 + 2][row] = rw.z;
        Ws[buf][kq * 4 + 3][row] = rw.w;
    };

    loadA(0);
    loadW(0);
    storeT(0);
    __syncthreads();

    const int tx = tid & 15;   // 16 n-pairs -> 32 n
    const int ty = tid >> 4;   // 16 m-quads -> 64 m
    const int mm = ty * 4;
    const int nn = tx * 2;

    unsigned long long acc0 = 0ULL, acc1 = 0ULL, acc2 = 0ULL, acc3 = 0ULL;

    const int NT = II / 32;
    for (int kt = 0; kt < NT; kt++) {
        const int buf = kt & 1;
        if (kt + 1 < NT) { loadA(kt + 1); loadW(kt + 1); }
#pragma unroll
        for (int k4 = 0; k4 < 32; k4 += 4) {
            float4 a0 = *(const float4*)&As[buf][mm + 0][k4];
            float4 a1 = *(const float4*)&As[buf][mm + 1][k4];
            float4 a2 = *(const float4*)&As[buf][mm + 2][k4];
            float4 a3 = *(const float4*)&As[buf][mm + 3][k4];
#pragma unroll
            for (int u = 0; u < 4; u++) {
                unsigned long long pb =
                    *(const unsigned long long*)&Ws[buf][k4 + u][nn];
                ffma2(acc0, dup2((&a0.x)[u]), pb);
                ffma2(acc1, dup2((&a1.x)[u]), pb);
                ffma2(acc2, dup2((&a2.x)[u]), pb);
                ffma2(acc3, dup2((&a3.x)[u]), pb);
            }
        }
        if (kt + 1 < NT) {
            storeT(buf ^ 1);
            __syncthreads();
        }
    }

    // Epilogue: add biases, scatter to g_xp[t][b][n]
    const int n = n0 + nn;
    const float bias0 = bih[n] + bhh[n];
    const float bias1 = bih[n + 1] + bhh[n + 1];

    unsigned long long accs[4] = {acc0, acc1, acc2, acc3};
#pragma unroll
    for (int j = 0; j < 4; j++) {
        float c0, c1;
        unpack2(accs[j], c0, c1);
        int r = r0 + mm + j;
        int b = r >> 9;        // / T
        int t = r & (TT - 1);  // % T
        float* dst = g_xp + (size_t)t * BH + (size_t)b * HH + n;
        dst[0] = c0 + bias0;
        dst[1] = c1 + bias1;
    }
}

// ---------------------------------------------------------------------------
// Phase 2: one recurrence step.
//   preact[b][n] = xp[t][b][n] + sum_k hprev[b][k] * W_hh[n][k]
//   out[b][t][n] = tanh(preact)
// Grid: (1024/16 n-tiles, 64/32 m-tiles) = 128 blocks, 128 threads.
// Block tile BM=32 x BN=16, full K=1024 (BK=64 double-buffered).
// Microtile 2m x 2n per thread via f32x2.
// ---------------------------------------------------------------------------
__global__ __launch_bounds__(128) void rnn_step_kernel(
    const float* __restrict__ hprev,   // [B] rows with stride hstride
    size_t hstride,
    const float* __restrict__ Whh,     // [H, H]
    int t,
    float* __restrict__ out_t)         // out + t*H ; element (b,n) at b*TH + n
{
    __shared__ float hs[2][32][64];    // [buf][m][k]
    __shared__ float ws[2][64][18];    // [buf][k][n] (transposed, padded)

    const int tid = threadIdx.x;
    const int m0 = blockIdx.y * 32;
    const int n0 = blockIdx.x * 16;

    float4 rh[4], rw[2];

    auto loadH = [&](int kt) {
#pragma unroll
        for (int i = 0; i < 4; i++) {
            int idx = tid + 128 * i;
            int row = idx >> 4, kq = idx & 15;
            rh[i] = *(const float4*)(hprev + (size_t)(m0 + row) * hstride +
                                     kt * 64 + kq * 4);
        }
    };
    auto loadW = [&](int kt) {
#pragma unroll
        for (int i = 0; i < 2; i++) {
            int idx = tid + 128 * i;
            int row = idx >> 4, kq = idx & 15;
            rw[i] = *(const float4*)(Whh + (size_t)(n0 + row) * HH +
                                     kt * 64 + kq * 4);
        }
    };
    auto storeT = [&](int buf) {
#pragma unroll
        for (int i = 0; i < 4; i++) {
            int idx = tid + 128 * i;
            int row = idx >> 4, kq = idx & 15;
            *(float4*)&hs[buf][row][kq * 4] = rh[i];
        }
#pragma unroll
        for (int i = 0; i < 2; i++) {
            int idx = tid + 128 * i;
            int row = idx >> 4, kq = idx & 15;
            ws[buf][kq * 4 + 0][row] = rw[i].x;
            ws[buf][kq * 4 + 1][row] = rw[i].y;
            ws[buf][kq * 4 + 2][row] = rw[i].z;
            ws[buf][kq * 4 + 3][row] = rw[i].w;
        }
    };

    loadH(0);
    loadW(0);
    storeT(0);
    __syncthreads();

    const int tx = tid & 7;    // 8 n-pairs -> 16 n
    const int ty = tid >> 3;   // 16 m-pairs -> 32 m
    const int mm = ty * 2;
    const int nn = tx * 2;

    unsigned long long acc0 = 0ULL, acc1 = 0ULL;

    const int NT = HH / 64;
    for (int kt = 0; kt < NT; kt++) {
        const int buf = kt & 1;
        if (kt + 1 < NT) { loadH(kt + 1); loadW(kt + 1); }
#pragma unroll
        for (int k4 = 0; k4 < 64; k4 += 4) {
            float4 a0 = *(const float4*)&hs[buf][mm + 0][k4];
            float4 a1 = *(const float4*)&hs[buf][mm + 1][k4];
#pragma unroll
            for (int u = 0; u < 4; u++) {
                unsigned long long pb =
                    *(const unsigned long long*)&ws[buf][k4 + u][nn];
                ffma2(acc0, dup2((&a0.x)[u]), pb);
                ffma2(acc1, dup2((&a1.x)[u]), pb);
            }
        }
        if (kt + 1 < NT) {
            storeT(buf ^ 1);
            __syncthreads();
        }
    }

    // Epilogue: add xp (already contains b_ih + b_hh), tanh, write h into out.
    const int m = m0 + mm;
    const int n = n0 + nn;
    const float* xpr0 = g_xp + (size_t)t * BH + (size_t)m * HH + n;
    const float* xpr1 = xpr0 + HH;

    float c00, c01, c10, c11;
    unpack2(acc0, c00, c01);
    unpack2(acc1, c10, c11);

    float* o0 = out_t + (size_t)m * TH + n;
    float* o1 = o0 + TH;
    o0[0] = tanhf(c00 + xpr0[0]);
    o0[1] = tanhf(c01 + xpr0[1]);
    o1[0] = tanhf(c10 + xpr1[0]);
    o1[1] = tanhf(c11 + xpr1[1]);
}

// ---------------------------------------------------------------------------
// Launch
// ---------------------------------------------------------------------------
extern "C" void kernel_launch(void* const* d_in, const int* in_sizes, int n_in,
                              void* d_out, int out_size) {
    const float* x    = (const float*)d_in[0];  // [B, T, I]
    const float* h0   = (const float*)d_in[1];  // [1, B, H]
    const float* W_ih = (const float*)d_in[2];  // [H, I]
    const float* b_ih = (const float*)d_in[3];  // [H]
    const float* W_hh = (const float*)d_in[4];  // [H, H]
    const float* b_hh = (const float*)d_in[5];  // [H]
    float* out = (float*)d_out;                 // [B, T, H]

    // Phase 1: input projection for all timesteps
    dim3 g1(HH / 32, (BB * TT) / 64);  // (32, 512)
    xp_gemm_kernel<<<g1, 256>>>(x, W_ih, b_ih, b_hh);

    // Phase 2: sequential recurrence, one kernel per timestep
    dim3 g2(HH / 16, BB / 32);  // (64, 2) = 128 blocks
    for (int t = 0; t < TT; t++) {
        const float* hprev = (t == 0) ? h0 : (out + (size_t)(t - 1) * HH);
        size_t hstride = (t == 0) ? (size_t)HH : TH;
        rnn_step_kernel<<<g2, 128>>>(hprev, hstride, W_hh, t,
                                     out + (size_t)t * HH);
    }
}

// round 13
// speedup vs baseline: 2.1650x; 2.1650x over previous
#include <cuda_runtime.h>
#include <cuda_bf16.h>
#include <math.h>

// Problem constants
#define BB 64
#define TT 512
#define II 1024
#define HH 1024
#define BH (BB * HH)         // 65536
#define TH ((size_t)TT * HH) // 524288

#define NBLOCKS 128

// Scratch: preactivation xp[t][b][h] = x@W_ih^T + b_ih + b_hh  (128 MB)
__device__ float g_xp[(size_t)TT * BB * HH];

// Grid-barrier state. g_bar_gen is MONOTONIC across graph replays: each block
// snapshots gen0 at kernel entry (before its first arrive), and barrier t
// releases when gen reaches gen0 + t + 1. g_bar_count is reset by the
// releaser (fenced before the gen bump), so it is 0 at every kernel entry.
__device__ unsigned g_bar_count;
__device__ unsigned g_bar_gen;

// ---------------------------------------------------------------------------
// f32x2 helpers (Blackwell packed fp32 FMA: 2 MACs per instruction)
// ---------------------------------------------------------------------------
__device__ __forceinline__ unsigned long long dup2(float v) {
    unsigned long long r;
    asm("mov.b64 %0, {%1, %1};" : "=l"(r) : "r"(__float_as_uint(v)));
    return r;
}
__device__ __forceinline__ void ffma2(unsigned long long& acc,
                                      unsigned long long a,
                                      unsigned long long b) {
    asm("fma.rn.f32x2 %0, %1, %2, %0;" : "+l"(acc) : "l"(a), "l"(b));
}
__device__ __forceinline__ void unpack2(unsigned long long v, float& lo, float& hi) {
    unsigned int l, h;
    asm("mov.b64 {%0, %1}, %2;" : "=r"(l), "=r"(h) : "l"(v));
    lo = __uint_as_float(l);
    hi = __uint_as_float(h);
}
__device__ __forceinline__ unsigned ld_acq(const unsigned* p) {
    unsigned v;
    asm volatile("ld.acquire.gpu.u32 %0, [%1];" : "=r"(v) : "l"(p));
    return v;
}

// ---------------------------------------------------------------------------
// Phase 1: xp GEMM.  C[r][n] = sum_i X[r][i] * W_ih[n][i],  r = b*T + t.
// (unchanged from the passing round)
// ---------------------------------------------------------------------------
__global__ __launch_bounds__(256) void xp_gemm_kernel(
    const float* __restrict__ X,     // [B*T, I]
    const float* __restrict__ Wih,   // [H, I]
    const float* __restrict__ bih,   // [H]
    const float* __restrict__ bhh)   // [H]
{
    __shared__ float As[2][64][32];
    __shared__ float Ws[2][32][34];

    const int tid = threadIdx.x;
    const int r0 = blockIdx.y * 64;
    const int n0 = blockIdx.x * 32;

    float4 ra[2], rw;

    auto loadA = [&](int kt) {
#pragma unroll
        for (int i = 0; i < 2; i++) {
            int idx = tid + 256 * i;
            int row = idx >> 3, kq = idx & 7;
            ra[i] = *(const float4*)(X + (size_t)(r0 + row) * II + kt * 32 + kq * 4);
        }
    };
    auto loadW = [&](int kt) {
        int row = tid >> 3, kq = tid & 7;
        rw = *(const float4*)(Wih + (size_t)(n0 + row) * II + kt * 32 + kq * 4);
    };
    auto storeT = [&](int buf) {
#pragma unroll
        for (int i = 0; i < 2; i++) {
            int idx = tid + 256 * i;
            int row = idx >> 3, kq = idx & 7;
            *(float4*)&As[buf][row][kq * 4] = ra[i];
        }
        int row = tid >> 3, kq = tid & 7;
        Ws[buf][kq * 4 + 0][row] = rw.x;
        Ws[buf][kq * 4 + 1][row] = rw.y;
        Ws[buf][kq * 4 + 2][row] = rw.z;
        Ws[buf][kq * 4 + 3][row] = rw.w;
    };

    loadA(0);
    loadW(0);
    storeT(0);
    __syncthreads();

    const int tx = tid & 15;
    const int ty = tid >> 4;
    const int mm = ty * 4;
    const int nn = tx * 2;

    unsigned long long acc0 = 0ULL, acc1 = 0ULL, acc2 = 0ULL, acc3 = 0ULL;

    const int NT = II / 32;
    for (int kt = 0; kt < NT; kt++) {
        const int buf = kt & 1;
        if (kt + 1 < NT) { loadA(kt + 1); loadW(kt + 1); }
#pragma unroll
        for (int k4 = 0; k4 < 32; k4 += 4) {
            float4 a0 = *(const float4*)&As[buf][mm + 0][k4];
            float4 a1 = *(const float4*)&As[buf][mm + 1][k4];
            float4 a2 = *(const float4*)&As[buf][mm + 2][k4];
            float4 a3 = *(const float4*)&As[buf][mm + 3][k4];
#pragma unroll
            for (int u = 0; u < 4; u++) {
                unsigned long long pb =
                    *(const unsigned long long*)&Ws[buf][k4 + u][nn];
                ffma2(acc0, dup2((&a0.x)[u]), pb);
                ffma2(acc1, dup2((&a1.x)[u]), pb);
                ffma2(acc2, dup2((&a2.x)[u]), pb);
                ffma2(acc3, dup2((&a3.x)[u]), pb);
            }
        }
        if (kt + 1 < NT) {
            storeT(buf ^ 1);
            __syncthreads();
        }
    }

    const int n = n0 + nn;
    const float bias0 = bih[n] + bhh[n];
    const float bias1 = bih[n + 1] + bhh[n + 1];

    unsigned long long accs[4] = {acc0, acc1, acc2, acc3};
#pragma unroll
    for (int j = 0; j < 4; j++) {
        float c0, c1;
        unpack2(accs[j], c0, c1);
        int r = r0 + mm + j;
        int b = r >> 9;
        int t = r & (TT - 1);
        float* dst = g_xp + (size_t)t * BH + (size_t)b * HH + n;
        dst[0] = c0 + bias0;
        dst[1] = c1 + bias1;
    }
}

// ---------------------------------------------------------------------------
// Phase 2: persistent recurrence kernel.
// Grid 128 blocks = 4 b-tiles (BM=16) x 32 n-tiles (BN=32), 256 threads.
// W_hh slice resident in smem (k-major, [1024][32] = 128 KB), loaded once.
// Per step: stage h slice into smem ([k][16], stride 20 -> 80 KB),
// 8 warps split K (128 each), microtile 4m x 4n via f32x2, fixed-order
// split-K combine in smem, tanh, write h into out[b][t][h], grid barrier.
// ---------------------------------------------------------------------------
#define HS_STRIDE 20
#define SMEM_WS   (1024 * 32)                  // floats
#define SMEM_HS   (1024 * HS_STRIDE)           // floats
#define SMEM_PS   (8 * 512)                    // floats
#define SMEM_FLOATS (SMEM_WS + SMEM_HS + SMEM_PS)
#define SMEM_BYTES  (SMEM_FLOATS * 4)          // 229376 B

__global__ __launch_bounds__(256, 1) void rnn_persistent_kernel(
    const float* __restrict__ h0,    // [B, H]
    const float* __restrict__ Whh,   // [H, H]
    float* __restrict__ out)         // [B, T, H]
{
    extern __shared__ float smem[];
    float* ws = smem;                 // [k][32]
    float* hs = smem + SMEM_WS;       // [k][HS_STRIDE], m in [0,16)
    float* ps = smem + SMEM_WS + SMEM_HS;  // [8][512]

    const int tid = threadIdx.x;
    const int n0 = blockIdx.x * 32;   // 32 n-tiles
    const int m0 = blockIdx.y * 16;   // 4 b-tiles

    // Snapshot barrier generation BEFORE any arrive (safe: no barrier can
    // complete until this block arrives, which is after this read).
    unsigned gen0 = 0;
    if (tid == 0) gen0 = ld_acq(&g_bar_gen);

    // ---- Stage W_hh slice once: ws[k*32 + n] = W_hh[n0+n][k] ----
#pragma unroll
    for (int i = 0; i < 32; i++) {
        int idx = tid + 256 * i;          // 0..8191
        int n = idx >> 8;                 // 0..31
        int f4 = idx & 255;               // 0..255
        float4 v = *(const float4*)(Whh + (size_t)(n0 + n) * HH + f4 * 4);
        ws[(f4 * 4 + 0) * 32 + n] = v.x;
        ws[(f4 * 4 + 1) * 32 + n] = v.y;
        ws[(f4 * 4 + 2) * 32 + n] = v.z;
        ws[(f4 * 4 + 3) * 32 + n] = v.w;
    }

    const int g = tid >> 5;           // warp = k-group (0..7)
    const int lane = tid & 31;
    const int mq = lane >> 3;         // 0..3  -> m = mq*4..mq*4+3
    const int nq = lane & 7;          // 0..7  -> n = nq*4..nq*4+3
    const int k0 = g * 128;

    for (int t = 0; t < TT; t++) {
        // ---- Stage h_{t-1} slice: hs[k*HS_STRIDE + b] = hprev[m0+b][k] ----
        const float* hsrc;
        size_t hstride;
        if (t == 0) { hsrc = h0 + (size_t)m0 * HH;                 hstride = HH; }
        else        { hsrc = out + (size_t)m0 * TH + (size_t)(t - 1) * HH; hstride = TH; }
#pragma unroll
        for (int i = 0; i < 16; i++) {
            int idx = tid + 256 * i;      // 0..4095
            int b = idx >> 8;             // 0..15
            int f4 = idx & 255;           // 0..255
            float4 v = *(const float4*)(hsrc + (size_t)b * hstride + f4 * 4);
            hs[(f4 * 4 + 0) * HS_STRIDE + b] = v.x;
            hs[(f4 * 4 + 1) * HS_STRIDE + b] = v.y;
            hs[(f4 * 4 + 2) * HS_STRIDE + b] = v.z;
            hs[(f4 * 4 + 3) * HS_STRIDE + b] = v.w;
        }
        __syncthreads();

        // ---- Compute: split-K, microtile 4m x 4n ----
        unsigned long long acc[8];
#pragma unroll
        for (int i = 0; i < 8; i++) acc[i] = 0ULL;

#pragma unroll 4
        for (int k = k0; k < k0 + 128; k++) {
            float4 av = *(const float4*)&hs[k * HS_STRIDE + mq * 4];
            ulonglong2 bv = *(const ulonglong2*)&ws[k * 32 + nq * 4];
#pragma unroll
            for (int i = 0; i < 4; i++) {
                unsigned long long ad = dup2((&av.x)[i]);
                ffma2(acc[2 * i + 0], ad, bv.x);
                ffma2(acc[2 * i + 1], ad, bv.y);
            }
        }

        // ---- Store partials: ps[g][ (mq*4+i)*32 + nq*4 + {0,2} ] ----
#pragma unroll
        for (int i = 0; i < 4; i++) {
            int o = g * 512 + (mq * 4 + i) * 32 + nq * 4;
            *(unsigned long long*)&ps[o + 0] = acc[2 * i + 0];
            *(unsigned long long*)&ps[o + 2] = acc[2 * i + 1];
        }
        __syncthreads();

        // ---- Combine (fixed order) + xp + tanh + write h into out ----
        {
            int o = tid * 2;              // 0..510
            int m = o >> 5;               // local b (0..15)
            int n = o & 31;               // local n (even)
            float s0 = 0.0f, s1 = 0.0f;
#pragma unroll
            for (int gg = 0; gg < 8; gg++) {
                float2 p = *(const float2*)&ps[gg * 512 + o];
                s0 += p.x;
                s1 += p.y;
            }
            const float* xpp = g_xp + (size_t)t * BH + (size_t)(m0 + m) * HH + n0 + n;
            float2 xv = *(const float2*)xpp;
            float r0 = tanhf(s0 + xv.x);
            float r1 = tanhf(s1 + xv.y);
            float* op = out + (size_t)(m0 + m) * TH + (size_t)t * HH + n0 + n;
            op[0] = r0;
            op[1] = r1;
        }

        // ---- Grid barrier: all h_t writes visible before any step t+1 read ----
        __syncthreads();
        if (tid == 0) {
            __threadfence();   // release this block's out-writes (gpu scope)
            unsigned old = atomicAdd(&g_bar_count, 1);
            unsigned target = gen0 + (unsigned)(t + 1);
            if (old == NBLOCKS - 1) {
                atomicExch(&g_bar_count, 0);
                __threadfence();
                atomicAdd(&g_bar_gen, 1);   // reaches target
            } else {
                while ((int)(ld_acq(&g_bar_gen) - target) < 0) {
                    __nanosleep(64);
                }
            }
        }
        __syncthreads();
    }
}

// ---------------------------------------------------------------------------
// Launch
// ---------------------------------------------------------------------------
extern "C" void kernel_launch(void* const* d_in, const int* in_sizes, int n_in,
                              void* d_out, int out_size) {
    const float* x    = (const float*)d_in[0];  // [B, T, I]
    const float* h0   = (const float*)d_in[1];  // [1, B, H]
    const float* W_ih = (const float*)d_in[2];  // [H, I]
    const float* b_ih = (const float*)d_in[3];  // [H]
    const float* W_hh = (const float*)d_in[4];  // [H, H]
    const float* b_hh = (const float*)d_in[5];  // [H]
    float* out = (float*)d_out;                 // [B, T, H]

    // Phase 1: input projection for all timesteps (biases folded in)
    dim3 g1(HH / 32, (BB * TT) / 64);  // (32, 512)
    xp_gemm_kernel<<<g1, 256>>>(x, W_ih, b_ih, b_hh);

    // Phase 2: persistent recurrence (single kernel, internal grid barriers)
    cudaFuncSetAttribute(rnn_persistent_kernel,
                         cudaFuncAttributeMaxDynamicSharedMemorySize, SMEM_BYTES);
    dim3 g2(32, 4);  // 128 blocks, all co-resident on 148 SMs
    rnn_persistent_kernel<<<g2, 256, SMEM_BYTES>>>(h0, W_hh, out);
}